// round 1
// baseline (speedup 1.0000x reference)
#include <cuda_runtime.h>
#include <math.h>

// Problem constants
#define B_ 16
#define C_ 512
#define N_ 4096

// Scratch (device globals: allocation inside kernel_launch is forbidden)
__device__ float g_G   [B_ * C_ * C_];  // X X^T per batch        (16 MB)
__device__ float g_T1  [B_ * C_ * C_];  // Wq G                   (16 MB)
__device__ float g_S   [B_ * C_ * C_];  // logits -> attn (inplace)(16 MB)
__device__ float g_Mv  [B_ * C_ * C_];  // attn Wv                (16 MB)
__device__ float g_r   [B_ * C_];       // row sums of X
__device__ float g_qr  [B_ * C_];       // Wq r
__device__ float g_kr  [B_ * C_];       // Wk r
__device__ float g_beta[B_ * C_];       // attn bv

// ---------------------------------------------------------------------------
// r[b,c] = sum_n X[b,c,n]
// ---------------------------------------------------------------------------
__global__ void __launch_bounds__(256) row_sum_kernel(const float* __restrict__ x,
                                                      float* __restrict__ r) {
    const int row = blockIdx.x;                 // b*C + c
    const float4* xr = (const float4*)(x + (size_t)row * N_);
    float s = 0.f;
    for (int i = threadIdx.x; i < N_ / 4; i += 256) {
        float4 v = xr[i];
        s += v.x + v.y + v.z + v.w;
    }
    __shared__ float sm[256];
    sm[threadIdx.x] = s;
    __syncthreads();
    #pragma unroll
    for (int off = 128; off > 0; off >>= 1) {
        if (threadIdx.x < off) sm[threadIdx.x] += sm[threadIdx.x + off];
        __syncthreads();
    }
    if (threadIdx.x == 0) r[row] = sm[0];
}

// ---------------------------------------------------------------------------
// qr[b] = Wq r[b],  kr[b] = Wk r[b]   (one warp per output element)
// ---------------------------------------------------------------------------
__global__ void __launch_bounds__(256) matvec_qk_kernel(const float* __restrict__ Wq,
                                                        const float* __restrict__ Wk,
                                                        const float* __restrict__ r,
                                                        float* __restrict__ qr,
                                                        float* __restrict__ kr) {
    const int b    = blockIdx.y;
    const int warp = threadIdx.x >> 5;
    const int lane = threadIdx.x & 31;
    const int o    = blockIdx.x * 8 + warp;
    const float* rb = r + b * C_;
    float sq = 0.f, sk = 0.f;
    for (int i = lane; i < C_; i += 32) {
        float rv = rb[i];
        sq += Wq[(size_t)o * C_ + i] * rv;
        sk += Wk[(size_t)o * C_ + i] * rv;
    }
    #pragma unroll
    for (int off = 16; off > 0; off >>= 1) {
        sq += __shfl_down_sync(0xFFFFFFFFu, sq, off);
        sk += __shfl_down_sync(0xFFFFFFFFu, sk, off);
    }
    if (lane == 0) {
        qr[b * C_ + o] = sq;
        kr[b * C_ + o] = sk;
    }
}

// ---------------------------------------------------------------------------
// Generic batched 128x128x8 tiled SGEMM, 8x8 register blocking, 256 threads.
// TRANS_B=false: C = A[M,K] * B[K,Nn]        (inner dim of B = Nn contiguous)
// TRANS_B=true : C = A[M,K] * B[Nn,K]^T      (inner dim of B = K contiguous)
// HAS_BIAS: C[m,n] += bias[b*sBias + m]
// Requires M,Nn multiples of 128 and K multiple of 8 (true for all uses).
// ---------------------------------------------------------------------------
template <bool TRANS_B, bool HAS_BIAS>
__global__ void __launch_bounds__(256, 1)
gemm128_kernel(const float* __restrict__ Ag, const float* __restrict__ Bg,
               float* __restrict__ Cg, int M, int Nn, int K,
               long long sA, long long sB, long long sC,
               const float* __restrict__ biasg, int sBias) {
    const int b = blockIdx.z;
    const float* A  = Ag + (size_t)b * sA;
    const float* Bp = Bg + (size_t)b * sB;
    float* Cp       = Cg + (size_t)b * sC;

    const int bn = blockIdx.x * 128;
    const int bm = blockIdx.y * 128;

    __shared__ float As[8][128];
    __shared__ float Bs[8][128];

    const int tid = threadIdx.x;
    const int tx = tid & 15;   // n direction (16)
    const int ty = tid >> 4;   // m direction (16)

    float acc[8][8];
    #pragma unroll
    for (int i = 0; i < 8; ++i)
        #pragma unroll
        for (int j = 0; j < 8; ++j) acc[i][j] = 0.f;

    // A-tile (and TRANS_B B-tile) load mapping: 128 rows x 8 k = 256 float4
    const int arow = tid >> 1;          // 0..127
    const int acol = (tid & 1) * 4;     // 0 or 4
    // NN B-tile load mapping: 8 k rows x 128 n = 256 float4
    const int bkrow = tid >> 5;         // 0..7
    const int bncol = (tid & 31) * 4;   // 0..124

    const float* Aptr = A + (size_t)(bm + arow) * K + acol;
    const float* Bptr = TRANS_B ? (Bp + (size_t)(bn + arow) * K + acol)
                                : (Bp + (size_t)bkrow * Nn + bn + bncol);

    for (int k0 = 0; k0 < K; k0 += 8) {
        float4 av = *(const float4*)Aptr;
        As[acol + 0][arow] = av.x;
        As[acol + 1][arow] = av.y;
        As[acol + 2][arow] = av.z;
        As[acol + 3][arow] = av.w;
        if (TRANS_B) {
            float4 bv = *(const float4*)Bptr;
            Bs[acol + 0][arow] = bv.x;
            Bs[acol + 1][arow] = bv.y;
            Bs[acol + 2][arow] = bv.z;
            Bs[acol + 3][arow] = bv.w;
        } else {
            *(float4*)&Bs[bkrow][bncol] = *(const float4*)Bptr;
        }
        __syncthreads();

        #pragma unroll
        for (int kk = 0; kk < 8; ++kk) {
            float ar[8], br[8];
            #pragma unroll
            for (int i = 0; i < 8; ++i) ar[i] = As[kk][ty * 8 + i];
            #pragma unroll
            for (int j = 0; j < 8; ++j) br[j] = Bs[kk][tx * 8 + j];
            #pragma unroll
            for (int i = 0; i < 8; ++i)
                #pragma unroll
                for (int j = 0; j < 8; ++j) acc[i][j] = fmaf(ar[i], br[j], acc[i][j]);
        }
        __syncthreads();

        Aptr += 8;
        if (TRANS_B) Bptr += 8; else Bptr += (size_t)8 * Nn;
    }

    #pragma unroll
    for (int i = 0; i < 8; ++i) {
        const int m = bm + ty * 8 + i;
        const float bias = HAS_BIAS ? biasg[(size_t)b * sBias + m] : 0.f;
        #pragma unroll
        for (int j = 0; j < 8; j += 4) {
            float4 v;
            v.x = acc[i][j + 0] + bias;
            v.y = acc[i][j + 1] + bias;
            v.z = acc[i][j + 2] + bias;
            v.w = acc[i][j + 3] + bias;
            *(float4*)&Cp[(size_t)m * Nn + bn + tx * 8 + j] = v;
        }
    }
}

// ---------------------------------------------------------------------------
// Fused: logits = (S + qr*bk^T + bq*kr^T + N*bq*bk^T)/sqrt(C); softmax rows;
// beta[row] = sum_d attn[row,d] * bv[d]. attn written in place over S.
// One block (256 threads) per row of 512.
// ---------------------------------------------------------------------------
__global__ void __launch_bounds__(256)
softmax_beta_kernel(float* __restrict__ S,
                    const float* __restrict__ qr, const float* __restrict__ kr,
                    const float* __restrict__ bq, const float* __restrict__ bk,
                    const float* __restrict__ bv, float* __restrict__ beta) {
    __shared__ float sm[256];
    const int row = blockIdx.x;        // b*C + c
    const int b = row >> 9;
    const int c = row & (C_ - 1);
    float* Sr = S + (size_t)row * C_;
    const float* krb = kr + b * C_;
    const float qrc = qr[row];
    const float bqc = bq[c];
    const float scale = rsqrtf((float)C_);
    const int t = threadIdx.x;

    float v[2];
    float mx = -1e30f;
    #pragma unroll
    for (int u = 0; u < 2; ++u) {
        const int d = t + u * 256;
        float s = (Sr[d] + qrc * bk[d] + bqc * krb[d] + (float)N_ * bqc * bk[d]) * scale;
        v[u] = s;
        mx = fmaxf(mx, s);
    }
    sm[t] = mx; __syncthreads();
    #pragma unroll
    for (int off = 128; off > 0; off >>= 1) {
        if (t < off) sm[t] = fmaxf(sm[t], sm[t + off]);
        __syncthreads();
    }
    mx = sm[0];
    __syncthreads();

    float sum = 0.f;
    #pragma unroll
    for (int u = 0; u < 2; ++u) {
        v[u] = expf(v[u] - mx);
        sum += v[u];
    }
    sm[t] = sum; __syncthreads();
    #pragma unroll
    for (int off = 128; off > 0; off >>= 1) {
        if (t < off) sm[t] += sm[t + off];
        __syncthreads();
    }
    const float inv = 1.f / sm[0];
    __syncthreads();

    float bc = 0.f;
    #pragma unroll
    for (int u = 0; u < 2; ++u) {
        const int d = t + u * 256;
        const float p = v[u] * inv;
        Sr[d] = p;
        bc += p * bv[d];
    }
    sm[t] = bc; __syncthreads();
    #pragma unroll
    for (int off = 128; off > 0; off >>= 1) {
        if (t < off) sm[t] += sm[t + off];
        __syncthreads();
    }
    if (t == 0) beta[row] = sm[0];
}

// ---------------------------------------------------------------------------
extern "C" void kernel_launch(void* const* d_in, const int* in_sizes, int n_in,
                              void* d_out, int out_size) {
    const float* x  = (const float*)d_in[0];
    const float* Wq = (const float*)d_in[1];
    const float* bq = (const float*)d_in[2];
    const float* Wk = (const float*)d_in[3];
    const float* bk = (const float*)d_in[4];
    const float* Wv = (const float*)d_in[5];
    const float* bv = (const float*)d_in[6];
    float* out = (float*)d_out;

    float *G, *T1, *S, *Mv, *r, *qr, *kr, *beta;
    cudaGetSymbolAddress((void**)&G,    g_G);
    cudaGetSymbolAddress((void**)&T1,   g_T1);
    cudaGetSymbolAddress((void**)&S,    g_S);
    cudaGetSymbolAddress((void**)&Mv,   g_Mv);
    cudaGetSymbolAddress((void**)&r,    g_r);
    cudaGetSymbolAddress((void**)&qr,   g_qr);
    cudaGetSymbolAddress((void**)&kr,   g_kr);
    cudaGetSymbolAddress((void**)&beta, g_beta);

    const long long CN = (long long)C_ * N_;   // 2097152
    const long long CC = (long long)C_ * C_;   // 262144

    // 1. r = X * 1
    row_sum_kernel<<<B_ * C_, 256>>>(x, r);

    // 2. G = X X^T (per batch), M=N=512, K=4096
    gemm128_kernel<true, false><<<dim3(4, 4, B_), 256>>>(
        x, x, G, C_, C_, N_, CN, CN, CC, nullptr, 0);

    // 3. qr = Wq r, kr = Wk r
    matvec_qk_kernel<<<dim3(C_ / 8, B_), 256>>>(Wq, Wk, r, qr, kr);

    // 4. T1 = Wq G
    gemm128_kernel<false, false><<<dim3(4, 4, B_), 256>>>(
        Wq, G, T1, C_, C_, C_, 0, CC, CC, nullptr, 0);

    // 5. S = T1 Wk^T
    gemm128_kernel<true, false><<<dim3(4, 4, B_), 256>>>(
        T1, Wk, S, C_, C_, C_, CC, 0, CC, nullptr, 0);

    // 6. softmax(+rank-1 bias corrections) -> attn (in place), beta = attn bv
    softmax_beta_kernel<<<B_ * C_, 256>>>(S, qr, kr, bq, bk, bv, beta);

    // 7. Mv = attn Wv
    gemm128_kernel<false, false><<<dim3(4, 4, B_), 256>>>(
        S, Wv, Mv, C_, C_, C_, CC, 0, CC, nullptr, 0);

    // 8. out = Mv X + beta
    gemm128_kernel<false, true><<<dim3(32, 4, B_), 256>>>(
        Mv, x, out, C_, N_, C_, CC, CN, CN, beta, C_);
}

// round 3
// speedup vs baseline: 2.7842x; 2.7842x over previous
#include <cuda_runtime.h>
#include <cuda_bf16.h>
#include <math.h>
#include <stdint.h>

#define B_ 16
#define C_ 512
#define N_ 4096

// ---------------------------------------------------------------------------
// Scratch (device globals; allocation in kernel_launch is forbidden)
// ---------------------------------------------------------------------------
__device__ __align__(1024) __nv_bfloat16 g_Xhi [(size_t)B_ * C_ * N_];
__device__ __align__(1024) __nv_bfloat16 g_Xlo [(size_t)B_ * C_ * N_];
__device__ __align__(1024) __nv_bfloat16 g_XThi[(size_t)B_ * N_ * C_];
__device__ __align__(1024) __nv_bfloat16 g_XTlo[(size_t)B_ * N_ * C_];
__device__ __align__(1024) __nv_bfloat16 g_Ghi [B_ * C_ * C_], g_Glo [B_ * C_ * C_];
__device__ __align__(1024) __nv_bfloat16 g_T1hi[B_ * C_ * C_], g_T1lo[B_ * C_ * C_];
__device__ __align__(1024) __nv_bfloat16 g_AThi[B_ * C_ * C_], g_ATlo[B_ * C_ * C_];
__device__ __align__(1024) __nv_bfloat16 g_Mvhi[B_ * C_ * C_], g_Mvlo[B_ * C_ * C_];
__device__ __align__(1024) __nv_bfloat16 g_Wqhi[C_ * C_], g_Wqlo[C_ * C_];
__device__ __align__(1024) __nv_bfloat16 g_Wkhi[C_ * C_], g_Wklo[C_ * C_];
__device__ __align__(1024) __nv_bfloat16 g_WvThi[C_ * C_], g_WvTlo[C_ * C_];
__device__ float g_S[B_ * C_ * C_];
__device__ float g_r[B_ * C_], g_qr[B_ * C_], g_kr[B_ * C_], g_beta[B_ * C_];

// ---------------------------------------------------------------------------
// Helpers
// ---------------------------------------------------------------------------
__device__ __forceinline__ uint32_t smem_u32(const void* p) {
    uint32_t a;
    asm("{ .reg .u64 t; cvta.to.shared.u64 t, %1; cvt.u32.u64 %0, t; }" : "=r"(a) : "l"(p));
    return a;
}
__device__ __forceinline__ uint32_t sw128(uint32_t off) { return off ^ ((off >> 3) & 0x70); }

__device__ __forceinline__ uint32_t cvt2(float lo, float hi) {
    uint32_t r; asm("cvt.rn.bf16x2.f32 %0, %1, %2;" : "=r"(r) : "f"(hi), "f"(lo)); return r;
}
__device__ __forceinline__ float lof(uint32_t h) { return __uint_as_float(h << 16); }
__device__ __forceinline__ float hif(uint32_t h) { return __uint_as_float(h & 0xFFFF0000u); }

#define CP_ASYNC16(dst, src) \
    asm volatile("cp.async.cg.shared.global [%0], [%1], 16;" :: "r"(dst), "l"(src))
#define CP_COMMIT() asm volatile("cp.async.commit_group;")
#define CP_WAIT0()  asm volatile("cp.async.wait_group 0;")
#define CP_WAIT1()  asm volatile("cp.async.wait_group 1;")

#define LDSM4(r0, r1, r2, r3, addr) \
    asm volatile("ldmatrix.sync.aligned.m8n8.x4.shared.b16 {%0,%1,%2,%3}, [%4];" \
                 : "=r"(r0), "=r"(r1), "=r"(r2), "=r"(r3) : "r"(addr))

#define MMA16816(c, a, b) \
    asm volatile("mma.sync.aligned.m16n8k16.row.col.f32.bf16.bf16.f32 " \
                 "{%0,%1,%2,%3},{%4,%5,%6,%7},{%8,%9},{%0,%1,%2,%3};" \
                 : "+f"((c)[0]), "+f"((c)[1]), "+f"((c)[2]), "+f"((c)[3]) \
                 : "r"((a)[0]), "r"((a)[1]), "r"((a)[2]), "r"((a)[3]), \
                   "r"((b)[0]), "r"((b)[1]))

// ---------------------------------------------------------------------------
// HMMA GEMM: D[m,n] = sum_k A[m,k]*B[n,k], both operands bf16 hi/lo planes,
// K-major. CTA 128x128, BK=64, 8 warps (64x32 each), cp.async double buffer.
// OM: 0 = fp32 out, 1 = bf16 hi/lo out, 2 = fp32 out + per-row bias.
// ---------------------------------------------------------------------------
#define GEMM_SMEM 131072    // 2 stages x (Ahi,Alo,Bhi,Blo) x 16KB

template <int OM>
__global__ void __launch_bounds__(256, 1)
gemm_mma(const __nv_bfloat16* __restrict__ Ahi, const __nv_bfloat16* __restrict__ Alo,
         int lda, long long sA,
         const __nv_bfloat16* __restrict__ Bhi, const __nv_bfloat16* __restrict__ Blo,
         int ldb, long long sB,
         float* __restrict__ Cf, __nv_bfloat16* __restrict__ Chi,
         __nv_bfloat16* __restrict__ Clo, int ldc, long long sC,
         const float* __restrict__ bias, int K) {
    extern __shared__ char smem[];
    const uint32_t sb = smem_u32(smem);

    const int tid = threadIdx.x;
    const int wid = tid >> 5;
    const int lane = tid & 31;
    const int bz = blockIdx.z;
    const int bm = blockIdx.y * 128;
    const int bn = blockIdx.x * 128;

    const __nv_bfloat16* Ah = Ahi + (size_t)bz * sA + (size_t)bm * lda;
    const __nv_bfloat16* Al = Alo + (size_t)bz * sA + (size_t)bm * lda;
    const __nv_bfloat16* Bh = Bhi + (size_t)bz * sB + (size_t)bn * ldb;
    const __nv_bfloat16* Bl = Blo + (size_t)bz * sB + (size_t)bn * ldb;

    // loader mapping: 1024 16B-chunks per plane; thread does 4 chunks/plane
    // chunk id = tid + 256*j : row = id>>3 (0..127), c = id&7 (16B col chunk)
    float acc[4][4][4];
    #pragma unroll
    for (int mi = 0; mi < 4; ++mi)
        #pragma unroll
        for (int ni = 0; ni < 4; ++ni)
            #pragma unroll
            for (int e = 0; e < 4; ++e) acc[mi][ni][e] = 0.f;

    const int nit = K >> 6;

    // -- stage loader --
    auto load_stage = [&](int s, int k0) {
        const uint32_t S = sb + (uint32_t)s * 65536u;
        #pragma unroll
        for (int j = 0; j < 4; ++j) {
            const int id = tid + 256 * j;
            const int row = id >> 3;
            const int c = id & 7;
            const uint32_t off = sw128((uint32_t)row * 128u + (uint32_t)c * 16u);
            const size_t ga = (size_t)row * lda + k0 + c * 8;
            const size_t gb = (size_t)row * ldb + k0 + c * 8;
            CP_ASYNC16(S + off,          Ah + ga);
            CP_ASYNC16(S + 16384 + off,  Al + ga);
            CP_ASYNC16(S + 32768 + off,  Bh + gb);
            CP_ASYNC16(S + 49152 + off,  Bl + gb);
        }
    };

    load_stage(0, 0);
    CP_COMMIT();
    if (nit > 1) { load_stage(1, 64); }
    CP_COMMIT();

    const int m0l = (wid & 1) * 64;
    const int n0l = (wid >> 1) * 32;

    for (int it = 0; it < nit; ++it) {
        if (it + 1 < nit) { CP_WAIT1(); } else { CP_WAIT0(); }
        __syncthreads();

        const uint32_t S = sb + (uint32_t)(it & 1) * 65536u;
        const uint32_t Sa = S;
        const uint32_t Sb = S + 32768;

        #pragma unroll
        for (int ks = 0; ks < 4; ++ks) {
            const uint32_t kb = (uint32_t)ks * 32u;
            uint32_t ah[4][4], al[4][4];
            #pragma unroll
            for (int mi = 0; mi < 4; ++mi) {
                const uint32_t ad = Sa + sw128(
                    (uint32_t)(m0l + mi * 16 + (lane & 15)) * 128u + kb + (uint32_t)(lane >> 4) * 16u);
                LDSM4(ah[mi][0], ah[mi][1], ah[mi][2], ah[mi][3], ad);
                LDSM4(al[mi][0], al[mi][1], al[mi][2], al[mi][3], ad + 16384);
            }
            uint32_t bh[4][2], bl[4][2];
            #pragma unroll
            for (int np = 0; np < 2; ++np) {
                const uint32_t bd = Sb + sw128(
                    (uint32_t)(n0l + np * 16 + (lane >> 4) * 8 + (lane & 7)) * 128u +
                    kb + (uint32_t)((lane >> 3) & 1) * 16u);
                uint32_t r0, r1, r2, r3;
                LDSM4(r0, r1, r2, r3, bd);
                bh[np * 2][0] = r0; bh[np * 2][1] = r1;
                bh[np * 2 + 1][0] = r2; bh[np * 2 + 1][1] = r3;
                LDSM4(r0, r1, r2, r3, bd + 16384);
                bl[np * 2][0] = r0; bl[np * 2][1] = r1;
                bl[np * 2 + 1][0] = r2; bl[np * 2 + 1][1] = r3;
            }
            #pragma unroll
            for (int mi = 0; mi < 4; ++mi)
                #pragma unroll
                for (int ni = 0; ni < 4; ++ni) {
                    MMA16816(acc[mi][ni], ah[mi], bh[ni]);
                    MMA16816(acc[mi][ni], al[mi], bh[ni]);
                    MMA16816(acc[mi][ni], ah[mi], bl[ni]);
                }
        }
        __syncthreads();
        if (it + 2 < nit) { load_stage(it & 1, (it + 2) * 64); }
        CP_COMMIT();
    }

    // ------------------------------- epilogue --------------------------------
    float* Cfb = Cf ? (Cf + (size_t)bz * sC) : nullptr;
    __nv_bfloat16* Chb = Chi ? (Chi + (size_t)bz * sC) : nullptr;
    __nv_bfloat16* Clb = Clo ? (Clo + (size_t)bz * sC) : nullptr;

    #pragma unroll
    for (int mi = 0; mi < 4; ++mi) {
        #pragma unroll
        for (int h = 0; h < 2; ++h) {
            const int row = bm + m0l + mi * 16 + (lane >> 2) + h * 8;
            float bb = 0.f;
            if (OM == 2) bb = bias[bz * C_ + row];
            #pragma unroll
            for (int ni = 0; ni < 4; ++ni) {
                const int col = bn + n0l + ni * 8 + (lane & 3) * 2;
                const float v0 = acc[mi][ni][h * 2 + 0];
                const float v1 = acc[mi][ni][h * 2 + 1];
                if (OM == 1) {
                    const uint32_t hh = cvt2(v0, v1);
                    const uint32_t ll = cvt2(v0 - lof(hh), v1 - hif(hh));
                    *(uint32_t*)(Chb + (size_t)row * ldc + col) = hh;
                    *(uint32_t*)(Clb + (size_t)row * ldc + col) = ll;
                } else {
                    float2 v; v.x = v0 + bb; v.y = v1 + bb;
                    *(float2*)(Cfb + (size_t)row * ldc + col) = v;
                }
            }
        }
    }
}

// ---------------------------------------------------------------------------
// Elementwise fp32 -> bf16 hi/lo split (vectorized, grid-stride over float4)
// ---------------------------------------------------------------------------
__global__ void __launch_bounds__(256)
split_kernel(const float* __restrict__ src, __nv_bfloat16* __restrict__ hi,
             __nv_bfloat16* __restrict__ lo, long long n4) {
    long long i = (long long)blockIdx.x * blockDim.x + threadIdx.x;
    const long long stride = (long long)gridDim.x * blockDim.x;
    const float4* s = (const float4*)src;
    uint2* hp = (uint2*)hi;
    uint2* lp = (uint2*)lo;
    for (; i < n4; i += stride) {
        float4 v = s[i];
        uint32_t h0 = cvt2(v.x, v.y), h1 = cvt2(v.z, v.w);
        uint32_t l0 = cvt2(v.x - lof(h0), v.y - hif(h0));
        uint32_t l1 = cvt2(v.z - lof(h1), v.w - hif(h1));
        hp[i] = make_uint2(h0, h1);
        lp[i] = make_uint2(l0, l1);
    }
}

// ---------------------------------------------------------------------------
// r[b,c] = sum_n X[b,c,n]
// ---------------------------------------------------------------------------
__global__ void __launch_bounds__(256) row_sum_kernel(const float* __restrict__ x,
                                                      float* __restrict__ r) {
    const int row = blockIdx.x;
    const float4* xr = (const float4*)(x + (size_t)row * N_);
    float s = 0.f;
    for (int i = threadIdx.x; i < N_ / 4; i += 256) {
        float4 v = xr[i];
        s += v.x + v.y + v.z + v.w;
    }
    __shared__ float sm[256];
    sm[threadIdx.x] = s;
    __syncthreads();
    #pragma unroll
    for (int off = 128; off > 0; off >>= 1) {
        if (threadIdx.x < off) sm[threadIdx.x] += sm[threadIdx.x + off];
        __syncthreads();
    }
    if (threadIdx.x == 0) r[row] = sm[0];
}

// ---------------------------------------------------------------------------
// qr = Wq r, kr = Wk r
// ---------------------------------------------------------------------------
__global__ void __launch_bounds__(256) matvec_qk_kernel(const float* __restrict__ Wq,
                                                        const float* __restrict__ Wk,
                                                        const float* __restrict__ r,
                                                        float* __restrict__ qr,
                                                        float* __restrict__ kr) {
    const int b = blockIdx.y;
    const int warp = threadIdx.x >> 5;
    const int lane = threadIdx.x & 31;
    const int o = blockIdx.x * 8 + warp;
    const float* rb = r + b * C_;
    float sq = 0.f, sk = 0.f;
    for (int i = lane; i < C_; i += 32) {
        float rv = rb[i];
        sq += Wq[(size_t)o * C_ + i] * rv;
        sk += Wk[(size_t)o * C_ + i] * rv;
    }
    #pragma unroll
    for (int off = 16; off > 0; off >>= 1) {
        sq += __shfl_down_sync(0xFFFFFFFFu, sq, off);
        sk += __shfl_down_sync(0xFFFFFFFFu, sk, off);
    }
    if (lane == 0) { qr[b * C_ + o] = sq; kr[b * C_ + o] = sk; }
}

// ---------------------------------------------------------------------------
// Transpose + bf16 split: src fp32 [R rows][Cc cols] -> dst hi/lo [Cc][R]
// ---------------------------------------------------------------------------
__global__ void __launch_bounds__(256)
transpose_cvt(const float* __restrict__ src, __nv_bfloat16* __restrict__ dhi,
              __nv_bfloat16* __restrict__ dlo, int R, int Cc,
              long long sSrc, long long sDst) {
    __shared__ float t[32][33];
    const int tx = threadIdx.x & 31, ty = threadIdx.x >> 5;
    const float* s = src + (size_t)blockIdx.z * sSrc;
    const int r0 = blockIdx.y * 32, c0 = blockIdx.x * 32;
    #pragma unroll
    for (int k = 0; k < 4; ++k)
        t[ty + 8 * k][tx] = s[(size_t)(r0 + ty + 8 * k) * Cc + c0 + tx];
    __syncthreads();
    const size_t db = (size_t)blockIdx.z * sDst;
    #pragma unroll
    for (int k = 0; k < 4; ++k) {
        const int i = ty + 8 * k;
        const float v = t[tx][i];
        __nv_bfloat16 h = __float2bfloat16(v);
        __nv_bfloat16 l = __float2bfloat16(v - __bfloat162float(h));
        const size_t o = db + (size_t)(c0 + i) * R + r0 + tx;
        dhi[o] = h; dlo[o] = l;
    }
}

// ---------------------------------------------------------------------------
// Softmax with rank-1 bias corrections; attn -> bf16 hi/lo planes + beta
// ---------------------------------------------------------------------------
__global__ void __launch_bounds__(256)
softmax_beta_kernel(const float* __restrict__ S,
                    const float* __restrict__ qr, const float* __restrict__ kr,
                    const float* __restrict__ bq, const float* __restrict__ bk,
                    const float* __restrict__ bv,
                    __nv_bfloat16* __restrict__ Ahi, __nv_bfloat16* __restrict__ Alo,
                    float* __restrict__ beta) {
    __shared__ float sm[256];
    const int row = blockIdx.x;
    const int b = row >> 9;
    const int c = row & (C_ - 1);
    const float* Sr = S + (size_t)row * C_;
    const float* krb = kr + b * C_;
    const float qrc = qr[row];
    const float bqc = bq[c];
    const float scale = rsqrtf((float)C_);
    const int t = threadIdx.x;

    float v[2];
    float mx = -1e30f;
    #pragma unroll
    for (int u = 0; u < 2; ++u) {
        const int d = t + u * 256;
        float s = (Sr[d] + qrc * bk[d] + bqc * krb[d] + (float)N_ * bqc * bk[d]) * scale;
        v[u] = s;
        mx = fmaxf(mx, s);
    }
    sm[t] = mx; __syncthreads();
    #pragma unroll
    for (int off = 128; off > 0; off >>= 1) {
        if (t < off) sm[t] = fmaxf(sm[t], sm[t + off]);
        __syncthreads();
    }
    mx = sm[0];
    __syncthreads();

    float sum = 0.f;
    #pragma unroll
    for (int u = 0; u < 2; ++u) { v[u] = expf(v[u] - mx); sum += v[u]; }
    sm[t] = sum; __syncthreads();
    #pragma unroll
    for (int off = 128; off > 0; off >>= 1) {
        if (t < off) sm[t] += sm[t + off];
        __syncthreads();
    }
    const float inv = 1.f / sm[0];
    __syncthreads();

    float bc = 0.f;
    #pragma unroll
    for (int u = 0; u < 2; ++u) {
        const int d = t + u * 256;
        const float p = v[u] * inv;
        __nv_bfloat16 h = __float2bfloat16(p);
        __nv_bfloat16 l = __float2bfloat16(p - __bfloat162float(h));
        Ahi[(size_t)row * C_ + d] = h;
        Alo[(size_t)row * C_ + d] = l;
        bc += p * bv[d];
    }
    sm[t] = bc; __syncthreads();
    #pragma unroll
    for (int off = 128; off > 0; off >>= 1) {
        if (t < off) sm[t] += sm[t + off];
        __syncthreads();
    }
    if (t == 0) beta[row] = sm[0];
}

// ---------------------------------------------------------------------------
extern "C" void kernel_launch(void* const* d_in, const int* in_sizes, int n_in,
                              void* d_out, int out_size) {
    const float* x  = (const float*)d_in[0];
    const float* Wq = (const float*)d_in[1];
    const float* bq = (const float*)d_in[2];
    const float* Wk = (const float*)d_in[3];
    const float* bk = (const float*)d_in[4];
    const float* Wv = (const float*)d_in[5];
    const float* bv = (const float*)d_in[6];
    float* out = (float*)d_out;

    __nv_bfloat16 *Xhi, *Xlo, *XThi, *XTlo, *Ghi, *Glo, *T1hi, *T1lo;
    __nv_bfloat16 *AThi, *ATlo, *Mvhi, *Mvlo, *Wqhi, *Wqlo, *Wkhi, *Wklo, *WvThi, *WvTlo;
    float *S, *r, *qr, *kr, *beta;
    cudaGetSymbolAddress((void**)&Xhi, g_Xhi);     cudaGetSymbolAddress((void**)&Xlo, g_Xlo);
    cudaGetSymbolAddress((void**)&XThi, g_XThi);   cudaGetSymbolAddress((void**)&XTlo, g_XTlo);
    cudaGetSymbolAddress((void**)&Ghi, g_Ghi);     cudaGetSymbolAddress((void**)&Glo, g_Glo);
    cudaGetSymbolAddress((void**)&T1hi, g_T1hi);   cudaGetSymbolAddress((void**)&T1lo, g_T1lo);
    cudaGetSymbolAddress((void**)&AThi, g_AThi);   cudaGetSymbolAddress((void**)&ATlo, g_ATlo);
    cudaGetSymbolAddress((void**)&Mvhi, g_Mvhi);   cudaGetSymbolAddress((void**)&Mvlo, g_Mvlo);
    cudaGetSymbolAddress((void**)&Wqhi, g_Wqhi);   cudaGetSymbolAddress((void**)&Wqlo, g_Wqlo);
    cudaGetSymbolAddress((void**)&Wkhi, g_Wkhi);   cudaGetSymbolAddress((void**)&Wklo, g_Wklo);
    cudaGetSymbolAddress((void**)&WvThi, g_WvThi); cudaGetSymbolAddress((void**)&WvTlo, g_WvTlo);
    cudaGetSymbolAddress((void**)&S, g_S);
    cudaGetSymbolAddress((void**)&r, g_r);   cudaGetSymbolAddress((void**)&qr, g_qr);
    cudaGetSymbolAddress((void**)&kr, g_kr); cudaGetSymbolAddress((void**)&beta, g_beta);

    const long long CN = (long long)C_ * N_;
    const long long CC = (long long)C_ * C_;
    const long long NC = (long long)N_ * C_;

    cudaFuncSetAttribute(gemm_mma<0>, cudaFuncAttributeMaxDynamicSharedMemorySize, GEMM_SMEM);
    cudaFuncSetAttribute(gemm_mma<1>, cudaFuncAttributeMaxDynamicSharedMemorySize, GEMM_SMEM);
    cudaFuncSetAttribute(gemm_mma<2>, cudaFuncAttributeMaxDynamicSharedMemorySize, GEMM_SMEM);

    // 1. row sums + operand prep
    row_sum_kernel<<<B_ * C_, 256>>>(x, r);
    split_kernel<<<4096, 256>>>(x, Xhi, Xlo, (long long)B_ * CN / 4);
    transpose_cvt<<<dim3(N_ / 32, C_ / 32, B_), 256>>>(x, XThi, XTlo, C_, N_, CN, NC);
    split_kernel<<<256, 256>>>(Wq, Wqhi, Wqlo, CC / 4);
    split_kernel<<<256, 256>>>(Wk, Wkhi, Wklo, CC / 4);
    transpose_cvt<<<dim3(C_ / 32, C_ / 32, 1), 256>>>(Wv, WvThi, WvTlo, C_, C_, 0, 0);
    matvec_qk_kernel<<<dim3(C_ / 8, B_), 256>>>(Wq, Wk, r, qr, kr);

    // 2. G = X X^T (bf16 hl out)
    gemm_mma<1><<<dim3(4, 4, B_), 256, GEMM_SMEM>>>(
        Xhi, Xlo, N_, CN,  Xhi, Xlo, N_, CN,
        nullptr, Ghi, Glo, C_, CC, nullptr, N_);

    // 3. T1 = Wq G (G symmetric -> B rows = G rows)
    gemm_mma<1><<<dim3(4, 4, B_), 256, GEMM_SMEM>>>(
        Wqhi, Wqlo, C_, 0,  Ghi, Glo, C_, CC,
        nullptr, T1hi, T1lo, C_, CC, nullptr, C_);

    // 4. S = T1 Wk^T (fp32 out)
    gemm_mma<0><<<dim3(4, 4, B_), 256, GEMM_SMEM>>>(
        T1hi, T1lo, C_, CC,  Wkhi, Wklo, C_, 0,
        S, nullptr, nullptr, C_, CC, nullptr, C_);

    // 5. softmax(+rank-1 corrections) -> attn hl, beta = attn bv
    softmax_beta_kernel<<<B_ * C_, 256>>>(S, qr, kr, bq, bk, bv, AThi, ATlo, beta);

    // 6. Mv = attn Wv   (B = WvT rows)
    gemm_mma<1><<<dim3(4, 4, B_), 256, GEMM_SMEM>>>(
        AThi, ATlo, C_, CC,  WvThi, WvTlo, C_, 0,
        nullptr, Mvhi, Mvlo, C_, CC, nullptr, C_);

    // 7. out = Mv X + beta   (B = XT rows)
    gemm_mma<2><<<dim3(32, 4, B_), 256, GEMM_SMEM>>>(
        Mvhi, Mvlo, C_, CC,  XThi, XTlo, C_, NC,
        out, nullptr, nullptr, N_, CN, beta, C_);
}